// round 17
// baseline (speedup 1.0000x reference)
#include <cuda_runtime.h>
#include <cuda_fp16.h>
#include <cstdint>

#define NUM_USERS 100000
#define NUM_ITEMS 50000
#define N_NODES   150000
#define C         64
#define NNZ       2400000
#define BATCH     8192
#define NEG_SLOPE 0.1f
#define EPS       1e-12f

// Normalized layer outputs p0,p1,p2 in fp16 (gather/score sources).
__device__ __half g_h[3][(size_t)N_NODES * C];
// fp16 RED accumulation targets. Layer1->rawA, 2->rawB, 3->rawA.
__device__ __half g_rawA[(size_t)N_NODES * C];
__device__ __half g_rawB[(size_t)N_NODES * C];
// Rows where layer-3 output is actually consumed (batch rows).
__device__ unsigned char g_needed[N_NODES];
// Compacted layer-3 edge list (destinations in needed set).
__device__ int   g_cr[NNZ];
__device__ int   g_cc[NNZ];
__device__ float g_cv[NNZ];
__device__ int   g_count;

__device__ __forceinline__ float lrelu(float x) {
    return x >= 0.0f ? x : NEG_SLOPE * x;
}

__device__ __forceinline__ float warp_sum(float s) {
#pragma unroll
    for (int o = 16; o; o >>= 1) s += __shfl_xor_sync(0xffffffffu, s, o);
    return s;
}

__device__ __forceinline__ float seg16_sum(float s) {
#pragma unroll
    for (int o = 8; o; o >>= 1) s += __shfl_xor_sync(0xffffffffu, s, o);
    return s;
}

// ---------------- zero fills (side stream) ----------------
// Full zero of one raw buffer: 1.2M uint4 stores.
__global__ __launch_bounds__(256) void k_zero_raw(int which) {
    uint4* dst = reinterpret_cast<uint4*>(which ? g_rawB : g_rawA);
    int i = blockIdx.x * blockDim.x + threadIdx.x;
    const int TOT = (int)((size_t)N_NODES * C * 2 / 16);   // 1.2M
    if (i < TOT) dst[i] = make_uint4(0u, 0u, 0u, 0u);
}

// Zero rawA only at needed rows (layer-3 scatter target is sparse).
__global__ __launch_bounds__(256) void k_zeroA_needed() {
    uint4* dst = reinterpret_cast<uint4*>(g_rawA);
    int i = blockIdx.x * blockDim.x + threadIdx.x;
    const int TOT = (int)((size_t)N_NODES * C * 2 / 16);
    if (i < TOT && g_needed[i >> 3]) dst[i] = make_uint4(0u, 0u, 0u, 0u);
}

// ---------------- needed-row bitmap ----------------
__global__ __launch_bounds__(256) void k_zero_needed() {
    int i = blockIdx.x * blockDim.x + threadIdx.x;
    if (i == 0) g_count = 0;
    if (i * 4 < N_NODES)
        reinterpret_cast<unsigned int*>(g_needed)[i] = 0u;
}

__global__ __launch_bounds__(256) void k_mark(const int* __restrict__ users,
                                              const int* __restrict__ adj,
                                              const int* __restrict__ weak,
                                              const int* __restrict__ strong) {
    int i = blockIdx.x * blockDim.x + threadIdx.x;
    if (i >= BATCH) return;
    g_needed[users[i]] = 1;
    g_needed[NUM_USERS + adj[i]] = 1;
    g_needed[NUM_USERS + weak[i]] = 1;
    g_needed[NUM_USERS + strong[i]] = 1;
}

// ---------------- compact layer-3 edges ----------------
// 4 edges/thread (int4 loads), warp scan + one atomicAdd per block.
__global__ __launch_bounds__(256) void k_compact(const int* __restrict__ erow,
                                                 const int* __restrict__ ecol,
                                                 const float* __restrict__ eval) {
    __shared__ int wtot[8];
    __shared__ int bbase;

    int t = blockIdx.x * blockDim.x + threadIdx.x;
    int e = t * 4;
    int lane = threadIdx.x & 31;
    int wid  = threadIdx.x >> 5;

    int4 r = make_int4(0, 0, 0, 0);
    bool a0 = false, a1 = false, a2 = false, a3 = false;
    if (e < NNZ) {
        r = __ldg(reinterpret_cast<const int4*>(erow + e));
        a0 = g_needed[r.x]; a1 = g_needed[r.y];
        a2 = g_needed[r.z]; a3 = g_needed[r.w];
    }
    int cnt = (int)a0 + (int)a1 + (int)a2 + (int)a3;

    int inc = cnt;
#pragma unroll
    for (int o = 1; o < 32; o <<= 1) {
        int n = __shfl_up_sync(0xffffffffu, inc, o);
        if (lane >= o) inc += n;
    }
    if (lane == 31) wtot[wid] = inc;
    __syncthreads();
    if (threadIdx.x == 0) {
        int tot = 0;
#pragma unroll
        for (int w = 0; w < 8; ++w) { int x = wtot[w]; wtot[w] = tot; tot += x; }
        bbase = tot ? atomicAdd(&g_count, tot) : 0;
    }
    __syncthreads();

    if (cnt) {
        int pos = bbase + wtot[wid] + (inc - cnt);
        int4   c = __ldg(reinterpret_cast<const int4*>(ecol + e));
        float4 v = __ldg(reinterpret_cast<const float4*>(eval + e));
        if (a0) { g_cr[pos] = r.x; g_cc[pos] = c.x; g_cv[pos] = v.x; ++pos; }
        if (a1) { g_cr[pos] = r.y; g_cc[pos] = c.y; g_cv[pos] = v.y; ++pos; }
        if (a2) { g_cr[pos] = r.z; g_cc[pos] = c.z; g_cv[pos] = v.z; ++pos; }
        if (a3) { g_cr[pos] = r.w; g_cc[pos] = c.w; g_cv[pos] = v.w; }
    }
}

// ---------------- init: normalize prefs -> h0 (fp16) ----------------
// 16 lanes/row, 4 rows/warp. (rawA zeroing moved to side stream.)
__global__ __launch_bounds__(256) void k_init(const float* __restrict__ up,
                                              const float* __restrict__ ip) {
    int warp = blockIdx.x * (blockDim.x >> 5) + (threadIdx.x >> 5);
    int rbase = warp * 4;
    if (rbase >= N_NODES) return;
    int lane = threadIdx.x & 31;
    int sub  = lane >> 4;
    int j    = lane & 15;

    int r0 = rbase + sub;
    int r1 = r0 + 2;

    const float* s0 = (r0 < NUM_USERS) ? up + (size_t)r0 * C
                                       : ip + (size_t)(r0 - NUM_USERS) * C;
    const float* s1 = (r1 < NUM_USERS) ? up + (size_t)r1 * C
                                       : ip + (size_t)(r1 - NUM_USERS) * C;

    float4 v0 = __ldg(reinterpret_cast<const float4*>(s0) + j);
    float4 v1 = __ldg(reinterpret_cast<const float4*>(s1) + j);

    v0.x = lrelu(v0.x); v0.y = lrelu(v0.y); v0.z = lrelu(v0.z); v0.w = lrelu(v0.w);
    v1.x = lrelu(v1.x); v1.y = lrelu(v1.y); v1.z = lrelu(v1.z); v1.w = lrelu(v1.w);

    float i0 = 1.0f / fmaxf(sqrtf(seg16_sum(v0.x*v0.x + v0.y*v0.y + v0.z*v0.z + v0.w*v0.w)), EPS);
    float i1 = 1.0f / fmaxf(sqrtf(seg16_sum(v1.x*v1.x + v1.y*v1.y + v1.z*v1.z + v1.w*v1.w)), EPS);

    __half2 a0 = __floats2half2_rn(v0.x * i0, v0.y * i0);
    __half2 b0 = __floats2half2_rn(v0.z * i0, v0.w * i0);
    __half2 a1 = __floats2half2_rn(v1.x * i1, v1.y * i1);
    __half2 b1 = __floats2half2_rn(v1.z * i1, v1.w * i1);

    uint2* h0 = reinterpret_cast<uint2*>(g_h[0]);
    h0[(size_t)r0 * 16 + j] =
        make_uint2(*reinterpret_cast<unsigned int*>(&a0), *reinterpret_cast<unsigned int*>(&b0));
    h0[(size_t)r1 * 16 + j] =
        make_uint2(*reinterpret_cast<unsigned int*>(&a1), *reinterpret_cast<unsigned int*>(&b1));
}

// ---------------- dense SpMM scatter (layers 1,2) ----------------
// 8 threads/edge, adjacent-edge pair per thread; vectorized edge metadata
// (__ldcs, evict-first) and fp16 HMUL2 inner math.
__global__ __launch_bounds__(256) void k_spmm(const int* __restrict__ erow,
                                              const int* __restrict__ ecol,
                                              const float* __restrict__ eval,
                                              int layer) {
    const __half* __restrict__ p = (layer == 1) ? g_h[0] : g_h[1];
    __half* __restrict__ pn      = (layer == 1) ? g_rawA : g_rawB;

    int tid = blockIdx.x * blockDim.x + threadIdx.x;
    int g = tid >> 3;
    int q = tid & 7;
    if (g >= NNZ / 2) return;
    int e = g * 2;

    int2   rr = __ldcs(reinterpret_cast<const int2*>(erow + e));
    int2   cc = __ldcs(reinterpret_cast<const int2*>(ecol + e));
    float2 vv = __ldcs(reinterpret_cast<const float2*>(eval + e));

    uint4 ha = __ldg(reinterpret_cast<const uint4*>(p + (size_t)cc.x * C + q * 8));
    uint4 hb = __ldg(reinterpret_cast<const uint4*>(p + (size_t)cc.y * C + q * 8));

    __half2 va = __float2half2_rn(vv.x);
    __half2 vb = __float2half2_rn(vv.y);

    unsigned int o0[4], o1[4];
    unsigned int* pa32 = reinterpret_cast<unsigned int*>(&ha);
    unsigned int* pb32 = reinterpret_cast<unsigned int*>(&hb);
#pragma unroll
    for (int k = 0; k < 4; ++k) {
        __half2 qa = __hmul2(*reinterpret_cast<__half2*>(&pa32[k]), va);
        __half2 qb = __hmul2(*reinterpret_cast<__half2*>(&pb32[k]), vb);
        o0[k] = *reinterpret_cast<unsigned int*>(&qa);
        o1[k] = *reinterpret_cast<unsigned int*>(&qb);
    }

    __half* d0 = pn + (size_t)rr.x * C + q * 8;
    __half* d1 = pn + (size_t)rr.y * C + q * 8;
    asm volatile("red.global.add.noftz.v4.f16x2 [%0], {%1,%2,%3,%4};"
                 :: "l"(d0), "r"(o0[0]), "r"(o0[1]), "r"(o0[2]), "r"(o0[3]) : "memory");
    asm volatile("red.global.add.noftz.v4.f16x2 [%0], {%1,%2,%3,%4};"
                 :: "l"(d1), "r"(o1[0]), "r"(o1[1]), "r"(o1[2]), "r"(o1[3]) : "memory");
}

// ---------------- compacted layer-3 SpMM: grid-stride over g_count edges ----------------
__global__ __launch_bounds__(256) void k_spmm3c() {
    const __half* __restrict__ p = g_h[2];
    __half* __restrict__ pn      = g_rawA;

    int cnt = g_count;
    int tid = blockIdx.x * blockDim.x + threadIdx.x;
    int G   = (gridDim.x * blockDim.x) >> 3;
    int q   = tid & 7;

    for (int e = tid >> 3; e < cnt; e += G) {
        int   r = g_cr[e];
        int   c = g_cc[e];
        float v = g_cv[e];

        uint4 h = __ldg(reinterpret_cast<const uint4*>(p + (size_t)c * C + q * 8));
        __half2 vh = __float2half2_rn(v);
        unsigned int o[4];
        unsigned int* hh = reinterpret_cast<unsigned int*>(&h);
#pragma unroll
        for (int k = 0; k < 4; ++k) {
            __half2 qv = __hmul2(*reinterpret_cast<__half2*>(&hh[k]), vh);
            o[k] = *reinterpret_cast<unsigned int*>(&qv);
        }
        __half* d = pn + (size_t)r * C + q * 8;
        asm volatile("red.global.add.noftz.v4.f16x2 [%0], {%1,%2,%3,%4};"
                     :: "l"(d), "r"(o[0]), "r"(o[1]), "r"(o[2]), "r"(o[3]) : "memory");
    }
}

// ---------------- norm: raw fp16 -> lrelu+l2norm -> fp16 (no zeroing) ----------------
// 16 lanes/row, 4 rows/warp.
__global__ __launch_bounds__(256) void k_norm(int layer) {
    const uint2* __restrict__ raw = reinterpret_cast<const uint2*>((layer == 1) ? g_rawA : g_rawB);
    uint2* __restrict__ hdst      = reinterpret_cast<uint2*>(g_h[layer]);

    int warp = blockIdx.x * (blockDim.x >> 5) + (threadIdx.x >> 5);
    int rbase = warp * 4;
    if (rbase >= N_NODES) return;
    int lane = threadIdx.x & 31;
    int sub  = lane >> 4;
    int j    = lane & 15;

    int r0 = rbase + sub;
    int r1 = r0 + 2;

    uint2 u0 = raw[(size_t)r0 * 16 + j];
    uint2 u1 = raw[(size_t)r1 * 16 + j];

    float2 x0 = __half22float2(*reinterpret_cast<__half2*>(&u0.x));
    float2 y0 = __half22float2(*reinterpret_cast<__half2*>(&u0.y));
    float2 x1 = __half22float2(*reinterpret_cast<__half2*>(&u1.x));
    float2 y1 = __half22float2(*reinterpret_cast<__half2*>(&u1.y));

    x0.x = lrelu(x0.x); x0.y = lrelu(x0.y); y0.x = lrelu(y0.x); y0.y = lrelu(y0.y);
    x1.x = lrelu(x1.x); x1.y = lrelu(x1.y); y1.x = lrelu(y1.x); y1.y = lrelu(y1.y);

    float i0 = 1.0f / fmaxf(sqrtf(seg16_sum(x0.x*x0.x + x0.y*x0.y + y0.x*y0.x + y0.y*y0.y)), EPS);
    float i1 = 1.0f / fmaxf(sqrtf(seg16_sum(x1.x*x1.x + x1.y*x1.y + y1.x*y1.x + y1.y*y1.y)), EPS);

    __half2 a0 = __floats2half2_rn(x0.x * i0, x0.y * i0);
    __half2 b0 = __floats2half2_rn(y0.x * i0, y0.y * i0);
    __half2 a1 = __floats2half2_rn(x1.x * i1, x1.y * i1);
    __half2 b1 = __floats2half2_rn(y1.x * i1, y1.y * i1);

    hdst[(size_t)r0 * 16 + j] =
        make_uint2(*reinterpret_cast<unsigned int*>(&a0), *reinterpret_cast<unsigned int*>(&b0));
    hdst[(size_t)r1 * 16 + j] =
        make_uint2(*reinterpret_cast<unsigned int*>(&a1), *reinterpret_cast<unsigned int*>(&b1));
}

// ---------------- scoring ----------------
__device__ __forceinline__ float2 merged_row(int row, int lane) {
    size_t idx = (size_t)row * 32 + lane;

    __half2 h0 = __ldg(&reinterpret_cast<const __half2*>(g_h[0])[idx]);
    __half2 h1 = __ldg(&reinterpret_cast<const __half2*>(g_h[1])[idx]);
    __half2 h2 = __ldg(&reinterpret_cast<const __half2*>(g_h[2])[idx]);
    float2 a3  = __half22float2(__ldg(&reinterpret_cast<const __half2*>(g_rawA)[idx]));

    a3.x = lrelu(a3.x);
    a3.y = lrelu(a3.y);
    float s = warp_sum(a3.x * a3.x + a3.y * a3.y);
    float inv = 1.0f / fmaxf(sqrtf(s), EPS);

    float2 f0 = __half22float2(h0);
    float2 f1 = __half22float2(h1);
    float2 f2 = __half22float2(h2);

    float2 m;
    m.x = f0.x + f1.x + f2.x + a3.x * inv;
    m.y = f0.y + f1.y + f2.y + a3.y * inv;
    return m;
}

__global__ __launch_bounds__(256) void k_score(const int* __restrict__ users,
                                               const int* __restrict__ adj,
                                               const int* __restrict__ weak,
                                               const int* __restrict__ strong,
                                               float* __restrict__ out) {
    int b = blockIdx.x * (blockDim.x >> 5) + (threadIdx.x >> 5);
    if (b >= BATCH) return;
    int lane = threadIdx.x & 31;

    float2 uv = merged_row(users[b], lane);
    float2 m0 = merged_row(NUM_USERS + adj[b], lane);
    float2 m1 = merged_row(NUM_USERS + weak[b], lane);
    float2 m2 = merged_row(NUM_USERS + strong[b], lane);

    float d0 = warp_sum(uv.x * m0.x + uv.y * m0.y);
    float d1 = warp_sum(uv.x * m1.x + uv.y * m1.y);
    float d2 = warp_sum(uv.x * m2.x + uv.y * m2.y);

    if (lane == 0) {
        out[0 * BATCH + b] = 1.0f / (1.0f + expf(-d0 * (1.0f / 16.0f)));
        out[1 * BATCH + b] = 1.0f / (1.0f + expf(-d1 * (1.0f / 16.0f)));
        out[2 * BATCH + b] = 1.0f / (1.0f + expf(-d2 * (1.0f / 16.0f)));
    }
}

extern "C" void kernel_launch(void* const* d_in, const int* in_sizes, int n_in,
                              void* d_out, int out_size) {
    const int*   users  = (const int*)d_in[0];
    const int*   adj    = (const int*)d_in[1];
    const int*   weak   = (const int*)d_in[2];
    const int*   strong = (const int*)d_in[3];
    const int*   erow   = (const int*)d_in[4];
    const int*   ecol   = (const int*)d_in[5];
    const float* eval   = (const float*)d_in[6];
    const float* up     = (const float*)d_in[7];
    const float* ip     = (const float*)d_in[8];
    float* out = (float*)d_out;

    const int ROW4_BLOCKS = (N_NODES + 31) / 32;
    const int SPMM_BLOCKS = ((NNZ / 2) * 8 + 255) / 256;
    const int ZERO_BLOCKS = ((int)((size_t)N_NODES * C * 2 / 16) + 255) / 256;

    // Side stream + events. Created fresh per call; intentionally not
    // destroyed mid-capture (would invalidate stream capture).
    cudaStream_t s2;
    cudaEvent_t ev_fork, ev_rA, ev_rB, ev_n1, ev_zn;
    cudaStreamCreateWithFlags(&s2, cudaStreamNonBlocking);
    cudaEventCreateWithFlags(&ev_fork, cudaEventDisableTiming);
    cudaEventCreateWithFlags(&ev_rA,   cudaEventDisableTiming);
    cudaEventCreateWithFlags(&ev_rB,   cudaEventDisableTiming);
    cudaEventCreateWithFlags(&ev_n1,   cudaEventDisableTiming);
    cudaEventCreateWithFlags(&ev_zn,   cudaEventDisableTiming);

    // Fork side branch.
    cudaEventRecord(ev_fork, 0);
    cudaStreamWaitEvent(s2, ev_fork, 0);

    // Side stream: zero rawA (for spmm1), zero rawB (for spmm2),
    // bitmap + compaction, then (after norm1) sparse rawA re-zero.
    k_zero_raw<<<ZERO_BLOCKS, 256, 0, s2>>>(0);
    cudaEventRecord(ev_rA, s2);
    k_zero_raw<<<ZERO_BLOCKS, 256, 0, s2>>>(1);
    cudaEventRecord(ev_rB, s2);
    k_zero_needed<<<(N_NODES / 4 + 255) / 256, 256, 0, s2>>>();
    k_mark<<<(BATCH + 255) / 256, 256, 0, s2>>>(users, adj, weak, strong);
    k_compact<<<(NNZ / 4 + 255) / 256, 256, 0, s2>>>(erow, ecol, eval);

    // Main stream: init + dense layers.
    k_init<<<ROW4_BLOCKS, 256>>>(up, ip);
    cudaStreamWaitEvent(0, ev_rA, 0);
    k_spmm<<<SPMM_BLOCKS, 256>>>(erow, ecol, eval, 1);   // h0 -> rawA
    k_norm<<<ROW4_BLOCKS, 256>>>(1);                     // rawA -> h1
    cudaEventRecord(ev_n1, 0);

    // Side stream: zero rawA at needed rows (must follow norm1's read of rawA).
    cudaStreamWaitEvent(s2, ev_n1, 0);
    k_zeroA_needed<<<ZERO_BLOCKS, 256, 0, s2>>>();
    cudaEventRecord(ev_zn, s2);

    cudaStreamWaitEvent(0, ev_rB, 0);
    k_spmm<<<SPMM_BLOCKS, 256>>>(erow, ecol, eval, 2);   // h1 -> rawB
    k_norm<<<ROW4_BLOCKS, 256>>>(2);                     // rawB -> h2

    // Join: spmm3c needs compacted edges (ordered before ev_zn on s2) and
    // the sparse rawA zeroing.
    cudaStreamWaitEvent(0, ev_zn, 0);
    k_spmm3c<<<2048, 256>>>();                           // compacted -> rawA

    k_score<<<(BATCH + 7) / 8, 256>>>(users, adj, weak, strong, out);
}